// round 2
// baseline (speedup 1.0000x reference)
#include <cuda_runtime.h>
#include <math.h>

#define BB   8
#define C1   512
#define C2   256
#define SD   512
#define H0   64
#define H1   128
#define NPIX   (H1*H1)      // 16384
#define NPIX0  (H0*H0)      // 4096

// ---------------- scratch (device globals; no allocation) ----------------
__device__ float g_s1[BB*C1];
__device__ float g_s2[BB*C2];
__device__ float g_s3[BB*C2];
__device__ float g_e1[BB*C2];
__device__ float g_e2[BB*C2];
__device__ float g_wsq1[C2*C1];
__device__ float g_wsq2[C2*C2];
__device__ float g_up [(size_t)BB*C1*NPIX];   // 268 MB
__device__ float g_h1 [(size_t)BB*C2*NPIX];   // 134 MB

// ---------------- styles: s = style @ (mod_w/sqrt(S)).T + mod_b ----------------
__global__ void k_styles(const float* __restrict__ w1, const float* __restrict__ w2,
                         const float* __restrict__ m1w, const float* __restrict__ m1b,
                         const float* __restrict__ m2w, const float* __restrict__ m2b,
                         const float* __restrict__ m3w, const float* __restrict__ m3b)
{
    int t = blockIdx.x*blockDim.x + threadIdx.x;
    const float inv = rsqrtf((float)SD);
    if (t < BB*C1) {
        int b = t / C1, i = t % C1;
        float a = 0.f;
        for (int k = 0; k < SD; k++) a += w1[b*SD+k] * m1w[i*SD+k];
        g_s1[t] = a*inv + m1b[i];
    } else if (t < BB*C1 + BB*C2) {
        int u = t - BB*C1; int b = u / C2, i = u % C2;
        float a = 0.f;
        for (int k = 0; k < SD; k++) a += w2[b*SD+k] * m2w[i*SD+k];
        g_s2[u] = a*inv + m2b[i];
    } else if (t < BB*C1 + 2*BB*C2) {
        int u = t - BB*C1 - BB*C2; int b = u / C2, i = u % C2;
        float a = 0.f;
        for (int k = 0; k < SD; k++) a += w2[b*SD+k] * m3w[i*SD+k];
        g_s3[u] = a*inv + m3b[i];
    }
}

// ---------------- per-(o,i) sum of squared 3x3 taps ----------------
__global__ void k_wsq(const float* __restrict__ w1c, const float* __restrict__ w2c)
{
    int t = blockIdx.x*blockDim.x + threadIdx.x;
    if (t < C2*C1) {
        float a = 0.f;
        #pragma unroll
        for (int k = 0; k < 9; k++) { float v = w1c[t*9+k]; a += v*v; }
        g_wsq1[t] = a;
    } else if (t < C2*C1 + C2*C2) {
        int u = t - C2*C1;
        float a = 0.f;
        #pragma unroll
        for (int k = 0; k < 9; k++) { float v = w2c[u*9+k]; a += v*v; }
        g_wsq2[u] = a;
    }
}

// ---------------- e[b,o] = scale * rsqrt(scale^2 * sum_i wsq[o,i]*s[b,i]^2 + eps) ----------------
__global__ void k_demod()
{
    int t = blockIdx.x*blockDim.x + threadIdx.x;
    const float sc1 = rsqrtf((float)(C1*9));
    const float sc2 = rsqrtf((float)(C2*9));
    if (t < BB*C2) {
        int b = t / C2, o = t % C2;
        float a = 0.f;
        for (int i = 0; i < C1; i++) { float s = g_s1[b*C1+i]; a += g_wsq1[o*C1+i]*s*s; }
        g_e1[t] = sc1 * rsqrtf(sc1*sc1*a + 1e-8f);
    } else if (t < 2*BB*C2) {
        int u = t - BB*C2; int b = u / C2, o = u % C2;
        float a = 0.f;
        for (int i = 0; i < C2; i++) { float s = g_s2[b*C2+i]; a += g_wsq2[o*C2+i]*s*s; }
        g_e2[u] = sc2 * rsqrtf(sc2*sc2*a + 1e-8f);
    }
}

// ---------------- bilinear 2x upsample (half-pixel, clamped) with s1 folded in ----------------
__global__ void k_upmod(const float* __restrict__ x)
{
    size_t t = (size_t)blockIdx.x*blockDim.x + threadIdx.x;
    if (t >= (size_t)BB*C1*NPIX) return;
    int p  = (int)(t % NPIX);
    int bc = (int)(t / NPIX);
    int X = p % H1, Y = p / H1;
    float sy = Y*0.5f - 0.25f, sx = X*0.5f - 0.25f;
    int y0 = (int)floorf(sy), x0 = (int)floorf(sx);
    float fy = sy - (float)y0, fx = sx - (float)x0;
    int y0c = max(y0, 0), y1c = min(y0+1, H0-1);
    int x0c = max(x0, 0), x1c = min(x0+1, H0-1);
    const float* xp = x + (size_t)bc*NPIX0;
    float v = (1.f-fy)*((1.f-fx)*xp[y0c*H0+x0c] + fx*xp[y0c*H0+x1c])
            +      fy *((1.f-fx)*xp[y1c*H0+x0c] + fx*xp[y1c*H0+x1c]);
    g_up[t] = v * g_s1[bc];
}

// ---------------- 3x3 conv, pad 1: 32 o-chans x (32x8) pixel tile per block ----------------
// 128 threads: po = tid/32 (4 o-subgroups of 8 chans), tx = tid%32 (x col, 8 y rows each)
template<int CIN, bool MODIN>
__global__ __launch_bounds__(128, 4)
void k_conv3x3(const float* __restrict__ in, const float* __restrict__ wgt,
               const float* __restrict__ smod, const float* __restrict__ emod,
               const float* __restrict__ noise, const float* __restrict__ nw,
               float* __restrict__ out)
{
    const int KC = 8, TO = 32;
    __shared__ float sIn[KC][10][34];
    __shared__ float sW [KC][9][TO+1];

    int tid = threadIdx.x;
    int po  = tid >> 5;
    int tx  = tid & 31;
    int bz  = blockIdx.z;
    int b   = bz >> 3;
    int o0  = (bz & 7) * TO;
    int gx0 = blockIdx.x * 32;
    int gy0 = blockIdx.y * 8;

    float acc[8][8];
    #pragma unroll
    for (int i = 0; i < 8; i++)
        #pragma unroll
        for (int j = 0; j < 8; j++) acc[i][j] = 0.f;

    for (int ci0 = 0; ci0 < CIN; ci0 += KC) {
        __syncthreads();
        // input tile 8 x 10 x 34 (halo, zero pad)
        for (int idx = tid; idx < KC*10*34; idx += 128) {
            int c = idx / 340, rem = idx % 340;
            int r = rem / 34, col = rem % 34;
            int gy = gy0 + r - 1, gx = gx0 + col - 1;
            float v = 0.f;
            if (gy >= 0 && gy < H1 && gx >= 0 && gx < H1) {
                v = in[(size_t)(b*CIN + ci0 + c)*NPIX + gy*H1 + gx];
                if (MODIN) v *= smod[b*CIN + ci0 + c];
            }
            sIn[c][r][col] = v;
        }
        // weights: per o, 72 consecutive floats (8 ci x 9 taps) -> coalesced
        for (int idx = tid; idx < TO*KC*9; idx += 128) {
            int o = idx / 72, rem = idx % 72;
            int c = rem / 9, tp = rem % 9;
            sW[c][tp][o] = wgt[(size_t)((o0 + o)*CIN + ci0 + c)*9 + tp];
        }
        __syncthreads();

        #pragma unroll
        for (int c = 0; c < KC; c++) {
            #pragma unroll
            for (int kx = 0; kx < 3; kx++) {
                float v[10];
                #pragma unroll
                for (int r = 0; r < 10; r++) v[r] = sIn[c][r][tx + kx];
                #pragma unroll
                for (int ky = 0; ky < 3; ky++) {
                    #pragma unroll
                    for (int oo = 0; oo < 8; oo++) {
                        float wv = sW[c][ky*3+kx][po*8 + oo];
                        #pragma unroll
                        for (int j = 0; j < 8; j++)
                            acc[oo][j] += wv * v[ky + j];
                    }
                }
            }
        }
    }

    float nwv = nw[0];
    #pragma unroll
    for (int oo = 0; oo < 8; oo++) {
        int o = o0 + po*8 + oo;
        float e = emod[b*C2 + o];
        #pragma unroll
        for (int j = 0; j < 8; j++) {
            int gy = gy0 + j, gx = gx0 + tx;
            float val = acc[oo][j]*e + nwv * noise[(size_t)b*NPIX + gy*H1 + gx];
            val = (val > 0.f) ? val : 0.2f*val;
            out[(size_t)(b*C2 + o)*NPIX + gy*H1 + gx] = val;
        }
    }
}

// ---------------- to_rgb 1x1 (no demod) + upsampled skip ----------------
__global__ void k_rgb(const float* __restrict__ h, const float* __restrict__ rgbw,
                      const float* __restrict__ skip, float* __restrict__ outrgb)
{
    int b = blockIdx.y;
    __shared__ float sw[3][C2];
    for (int i = threadIdx.x; i < 3*C2; i += blockDim.x) {
        int c = i / C2, o = i % C2;
        sw[c][o] = rgbw[c*C2 + o] * g_s3[b*C2 + o] * 0.0625f;  // scale3 = 1/sqrt(256)
    }
    __syncthreads();
    int p = blockIdx.x*blockDim.x + threadIdx.x;  // exact cover: 64*256 = 16384
    float a0 = 0.f, a1 = 0.f, a2 = 0.f;
    for (int o = 0; o < C2; o++) {
        float v = h[(size_t)(b*C2 + o)*NPIX + p];
        a0 += sw[0][o]*v; a1 += sw[1][o]*v; a2 += sw[2][o]*v;
    }
    int X = p % H1, Y = p / H1;
    float sy = Y*0.5f - 0.25f, sx = X*0.5f - 0.25f;
    int y0 = (int)floorf(sy), x0 = (int)floorf(sx);
    float fy = sy - (float)y0, fx = sx - (float)x0;
    int y0c = max(y0, 0), y1c = min(y0+1, H0-1);
    int x0c = max(x0, 0), x1c = min(x0+1, H0-1);
    float a[3] = {a0, a1, a2};
    #pragma unroll
    for (int c = 0; c < 3; c++) {
        const float* sp = skip + (size_t)(b*3 + c)*NPIX0;
        float bv = (1.f-fy)*((1.f-fx)*sp[y0c*H0+x0c] + fx*sp[y0c*H0+x1c])
                 +      fy *((1.f-fx)*sp[y1c*H0+x0c] + fx*sp[y1c*H0+x1c]);
        outrgb[(size_t)(b*3 + c)*NPIX + p] = a[c] + bv;
    }
}

// ---------------- launch ----------------
extern "C" void kernel_launch(void* const* d_in, const int* in_sizes, int n_in,
                              void* d_out, int out_size)
{
    const float* x       = (const float*)d_in[0];
    const float* w1      = (const float*)d_in[1];
    const float* w2      = (const float*)d_in[2];
    const float* skip    = (const float*)d_in[3];
    const float* noise1  = (const float*)d_in[4];
    const float* noise2  = (const float*)d_in[5];
    const float* conv1_w = (const float*)d_in[6];
    const float* mod1_w  = (const float*)d_in[7];
    const float* mod1_b  = (const float*)d_in[8];
    const float* conv2_w = (const float*)d_in[9];
    const float* mod2_w  = (const float*)d_in[10];
    const float* mod2_b  = (const float*)d_in[11];
    const float* rgb_w   = (const float*)d_in[12];
    const float* mod3_w  = (const float*)d_in[13];
    const float* mod3_b  = (const float*)d_in[14];
    const float* nw1     = (const float*)d_in[15];
    const float* nw2     = (const float*)d_in[16];
    float* out = (float*)d_out;

    float *p_up, *p_h1, *p_e1, *p_e2, *p_s2;
    cudaGetSymbolAddress((void**)&p_up, g_up);
    cudaGetSymbolAddress((void**)&p_h1, g_h1);
    cudaGetSymbolAddress((void**)&p_e1, g_e1);
    cudaGetSymbolAddress((void**)&p_e2, g_e2);
    cudaGetSymbolAddress((void**)&p_s2, g_s2);

    float* out_h   = out;                                // [8,256,128,128]
    float* out_rgb = out + (size_t)BB*C2*NPIX;           // [8,3,128,128]

    // 1. styles
    {
        int n = BB*C1 + 2*BB*C2;
        k_styles<<<(n + 255)/256, 256>>>(w1, w2, mod1_w, mod1_b, mod2_w, mod2_b, mod3_w, mod3_b);
    }
    // 2. weight square sums
    {
        int n = C2*C1 + C2*C2;
        k_wsq<<<(n + 255)/256, 256>>>(conv1_w, conv2_w);
    }
    // 3. demod scalars
    k_demod<<<(2*BB*C2 + 255)/256, 256>>>();
    // 4. upsample + modulate (s1)
    {
        size_t n = (size_t)BB*C1*NPIX;
        k_upmod<<<(unsigned)((n + 255)/256), 256>>>(x);
    }
    // 5. conv1 (input pre-modulated) -> g_h1, epilogue noise1 + lrelu
    k_conv3x3<C1, false><<<dim3(4, 16, BB*8), 128>>>(p_up, conv1_w, nullptr, p_e1, noise1, nw1, p_h1);
    // 6. conv2 (modulate by s2 at load) -> d_out h region, epilogue noise2 + lrelu
    k_conv3x3<C2, true ><<<dim3(4, 16, BB*8), 128>>>(p_h1, conv2_w, p_s2, p_e2, noise2, nw2, out_h);
    // 7. to_rgb + upsampled skip -> d_out rgb region
    k_rgb<<<dim3(NPIX/256, BB), 256>>>(out_h, rgb_w, skip, out_rgb);
}

// round 3
// speedup vs baseline: 1.0005x; 1.0005x over previous
#include <cuda_runtime.h>
#include <math.h>

#define BB   8
#define C1   512
#define C2   256
#define SD   512
#define H0   64
#define H1   128
#define NPIX   (H1*H1)      // 16384
#define NPIX0  (H0*H0)      // 4096

// ---------------- scratch (device globals; no allocation) ----------------
__device__ float g_s1[BB*C1];
__device__ float g_s2[BB*C2];
__device__ float g_s3[BB*C2];
__device__ float g_e1[BB*C2];
__device__ float g_e2[BB*C2];
__device__ float g_wsq1[C2*C1];
__device__ float g_wsq2[C2*C2];
__device__ float g_up [(size_t)BB*C1*NPIX];   // 268 MB
__device__ float g_h1 [(size_t)BB*C2*NPIX];   // 134 MB

// ---------------- styles: s = style @ (mod_w/sqrt(S)).T + mod_b ----------------
__global__ void k_styles(const float* __restrict__ w1, const float* __restrict__ w2,
                         const float* __restrict__ m1w, const float* __restrict__ m1b,
                         const float* __restrict__ m2w, const float* __restrict__ m2b,
                         const float* __restrict__ m3w, const float* __restrict__ m3b)
{
    int t = blockIdx.x*blockDim.x + threadIdx.x;
    const float inv = rsqrtf((float)SD);
    if (t < BB*C1) {
        int b = t / C1, i = t % C1;
        float a = 0.f;
        for (int k = 0; k < SD; k++) a += w1[b*SD+k] * m1w[i*SD+k];
        g_s1[t] = a*inv + m1b[i];
    } else if (t < BB*C1 + BB*C2) {
        int u = t - BB*C1; int b = u / C2, i = u % C2;
        float a = 0.f;
        for (int k = 0; k < SD; k++) a += w2[b*SD+k] * m2w[i*SD+k];
        g_s2[u] = a*inv + m2b[i];
    } else if (t < BB*C1 + 2*BB*C2) {
        int u = t - BB*C1 - BB*C2; int b = u / C2, i = u % C2;
        float a = 0.f;
        for (int k = 0; k < SD; k++) a += w2[b*SD+k] * m3w[i*SD+k];
        g_s3[u] = a*inv + m3b[i];
    }
}

// ---------------- per-(o,i) sum of squared 3x3 taps ----------------
__global__ void k_wsq(const float* __restrict__ w1c, const float* __restrict__ w2c)
{
    int t = blockIdx.x*blockDim.x + threadIdx.x;
    if (t < C2*C1) {
        float a = 0.f;
        #pragma unroll
        for (int k = 0; k < 9; k++) { float v = w1c[t*9+k]; a += v*v; }
        g_wsq1[t] = a;
    } else if (t < C2*C1 + C2*C2) {
        int u = t - C2*C1;
        float a = 0.f;
        #pragma unroll
        for (int k = 0; k < 9; k++) { float v = w2c[u*9+k]; a += v*v; }
        g_wsq2[u] = a;
    }
}

// ---------------- e[b,o] = scale * rsqrt(scale^2 * sum_i wsq[o,i]*s[b,i]^2 + eps) ----------------
__global__ void k_demod()
{
    int t = blockIdx.x*blockDim.x + threadIdx.x;
    const float sc1 = rsqrtf((float)(C1*9));
    const float sc2 = rsqrtf((float)(C2*9));
    if (t < BB*C2) {
        int b = t / C2, o = t % C2;
        float a = 0.f;
        for (int i = 0; i < C1; i++) { float s = g_s1[b*C1+i]; a += g_wsq1[o*C1+i]*s*s; }
        g_e1[t] = sc1 * rsqrtf(sc1*sc1*a + 1e-8f);
    } else if (t < 2*BB*C2) {
        int u = t - BB*C2; int b = u / C2, o = u % C2;
        float a = 0.f;
        for (int i = 0; i < C2; i++) { float s = g_s2[b*C2+i]; a += g_wsq2[o*C2+i]*s*s; }
        g_e2[u] = sc2 * rsqrtf(sc2*sc2*a + 1e-8f);
    }
}

// ---------------- bilinear 2x upsample (half-pixel, clamped) with s1 folded in ----------------
__global__ void k_upmod(const float* __restrict__ x)
{
    size_t t = (size_t)blockIdx.x*blockDim.x + threadIdx.x;
    if (t >= (size_t)BB*C1*NPIX) return;
    int p  = (int)(t % NPIX);
    int bc = (int)(t / NPIX);
    int X = p % H1, Y = p / H1;
    float sy = Y*0.5f - 0.25f, sx = X*0.5f - 0.25f;
    int y0 = (int)floorf(sy), x0 = (int)floorf(sx);
    float fy = sy - (float)y0, fx = sx - (float)x0;
    int y0c = max(y0, 0), y1c = min(y0+1, H0-1);
    int x0c = max(x0, 0), x1c = min(x0+1, H0-1);
    const float* xp = x + (size_t)bc*NPIX0;
    float v = (1.f-fy)*((1.f-fx)*xp[y0c*H0+x0c] + fx*xp[y0c*H0+x1c])
            +      fy *((1.f-fx)*xp[y1c*H0+x0c] + fx*xp[y1c*H0+x1c]);
    g_up[t] = v * g_s1[bc];
}

// ---------------- 3x3 conv, pad 1: 32 o-chans x (32x8) pixel tile per block ----------------
// 128 threads: po = tid/32 (4 o-subgroups of 8 chans), tx = tid%32 (x col, 8 y rows each)
template<int CIN, bool MODIN>
__global__ __launch_bounds__(128, 4)
void k_conv3x3(const float* __restrict__ in, const float* __restrict__ wgt,
               const float* __restrict__ smod, const float* __restrict__ emod,
               const float* __restrict__ noise, const float* __restrict__ nw,
               float* __restrict__ out)
{
    const int KC = 8, TO = 32;
    __shared__ float sIn[KC][10][34];
    __shared__ float sW [KC][9][TO+1];

    int tid = threadIdx.x;
    int po  = tid >> 5;
    int tx  = tid & 31;
    int bz  = blockIdx.z;
    int b   = bz >> 3;
    int o0  = (bz & 7) * TO;
    int gx0 = blockIdx.x * 32;
    int gy0 = blockIdx.y * 8;

    float acc[8][8];
    #pragma unroll
    for (int i = 0; i < 8; i++)
        #pragma unroll
        for (int j = 0; j < 8; j++) acc[i][j] = 0.f;

    for (int ci0 = 0; ci0 < CIN; ci0 += KC) {
        __syncthreads();
        // input tile 8 x 10 x 34 (halo, zero pad)
        for (int idx = tid; idx < KC*10*34; idx += 128) {
            int c = idx / 340, rem = idx % 340;
            int r = rem / 34, col = rem % 34;
            int gy = gy0 + r - 1, gx = gx0 + col - 1;
            float v = 0.f;
            if (gy >= 0 && gy < H1 && gx >= 0 && gx < H1) {
                v = in[(size_t)(b*CIN + ci0 + c)*NPIX + gy*H1 + gx];
                if (MODIN) v *= smod[b*CIN + ci0 + c];
            }
            sIn[c][r][col] = v;
        }
        // weights: per o, 72 consecutive floats (8 ci x 9 taps) -> coalesced
        for (int idx = tid; idx < TO*KC*9; idx += 128) {
            int o = idx / 72, rem = idx % 72;
            int c = rem / 9, tp = rem % 9;
            sW[c][tp][o] = wgt[(size_t)((o0 + o)*CIN + ci0 + c)*9 + tp];
        }
        __syncthreads();

        #pragma unroll
        for (int c = 0; c < KC; c++) {
            #pragma unroll
            for (int kx = 0; kx < 3; kx++) {
                float v[10];
                #pragma unroll
                for (int r = 0; r < 10; r++) v[r] = sIn[c][r][tx + kx];
                #pragma unroll
                for (int ky = 0; ky < 3; ky++) {
                    #pragma unroll
                    for (int oo = 0; oo < 8; oo++) {
                        float wv = sW[c][ky*3+kx][po*8 + oo];
                        #pragma unroll
                        for (int j = 0; j < 8; j++)
                            acc[oo][j] += wv * v[ky + j];
                    }
                }
            }
        }
    }

    float nwv = nw[0];
    #pragma unroll
    for (int oo = 0; oo < 8; oo++) {
        int o = o0 + po*8 + oo;
        float e = emod[b*C2 + o];
        #pragma unroll
        for (int j = 0; j < 8; j++) {
            int gy = gy0 + j, gx = gx0 + tx;
            float val = acc[oo][j]*e + nwv * noise[(size_t)b*NPIX + gy*H1 + gx];
            val = (val > 0.f) ? val : 0.2f*val;
            out[(size_t)(b*C2 + o)*NPIX + gy*H1 + gx] = val;
        }
    }
}

// ---------------- to_rgb 1x1 (no demod) + upsampled skip ----------------
__global__ void k_rgb(const float* __restrict__ h, const float* __restrict__ rgbw,
                      const float* __restrict__ skip, float* __restrict__ outrgb)
{
    int b = blockIdx.y;
    __shared__ float sw[3][C2];
    for (int i = threadIdx.x; i < 3*C2; i += blockDim.x) {
        int c = i / C2, o = i % C2;
        sw[c][o] = rgbw[c*C2 + o] * g_s3[b*C2 + o] * 0.0625f;  // scale3 = 1/sqrt(256)
    }
    __syncthreads();
    int p = blockIdx.x*blockDim.x + threadIdx.x;  // exact cover: 64*256 = 16384
    float a0 = 0.f, a1 = 0.f, a2 = 0.f;
    for (int o = 0; o < C2; o++) {
        float v = h[(size_t)(b*C2 + o)*NPIX + p];
        a0 += sw[0][o]*v; a1 += sw[1][o]*v; a2 += sw[2][o]*v;
    }
    int X = p % H1, Y = p / H1;
    float sy = Y*0.5f - 0.25f, sx = X*0.5f - 0.25f;
    int y0 = (int)floorf(sy), x0 = (int)floorf(sx);
    float fy = sy - (float)y0, fx = sx - (float)x0;
    int y0c = max(y0, 0), y1c = min(y0+1, H0-1);
    int x0c = max(x0, 0), x1c = min(x0+1, H0-1);
    float a[3] = {a0, a1, a2};
    #pragma unroll
    for (int c = 0; c < 3; c++) {
        const float* sp = skip + (size_t)(b*3 + c)*NPIX0;
        float bv = (1.f-fy)*((1.f-fx)*sp[y0c*H0+x0c] + fx*sp[y0c*H0+x1c])
                 +      fy *((1.f-fx)*sp[y1c*H0+x0c] + fx*sp[y1c*H0+x1c]);
        outrgb[(size_t)(b*3 + c)*NPIX + p] = a[c] + bv;
    }
}

// ---------------- launch ----------------
extern "C" void kernel_launch(void* const* d_in, const int* in_sizes, int n_in,
                              void* d_out, int out_size)
{
    const float* x       = (const float*)d_in[0];
    const float* w1      = (const float*)d_in[1];
    const float* w2      = (const float*)d_in[2];
    const float* skip    = (const float*)d_in[3];
    const float* noise1  = (const float*)d_in[4];
    const float* noise2  = (const float*)d_in[5];
    const float* conv1_w = (const float*)d_in[6];
    const float* mod1_w  = (const float*)d_in[7];
    const float* mod1_b  = (const float*)d_in[8];
    const float* conv2_w = (const float*)d_in[9];
    const float* mod2_w  = (const float*)d_in[10];
    const float* mod2_b  = (const float*)d_in[11];
    const float* rgb_w   = (const float*)d_in[12];
    const float* mod3_w  = (const float*)d_in[13];
    const float* mod3_b  = (const float*)d_in[14];
    const float* nw1     = (const float*)d_in[15];
    const float* nw2     = (const float*)d_in[16];
    float* out = (float*)d_out;

    float *p_up, *p_h1, *p_e1, *p_e2, *p_s2;
    cudaGetSymbolAddress((void**)&p_up, g_up);
    cudaGetSymbolAddress((void**)&p_h1, g_h1);
    cudaGetSymbolAddress((void**)&p_e1, g_e1);
    cudaGetSymbolAddress((void**)&p_e2, g_e2);
    cudaGetSymbolAddress((void**)&p_s2, g_s2);

    float* out_h   = out;                                // [8,256,128,128]
    float* out_rgb = out + (size_t)BB*C2*NPIX;           // [8,3,128,128]

    // 1. styles
    {
        int n = BB*C1 + 2*BB*C2;
        k_styles<<<(n + 255)/256, 256>>>(w1, w2, mod1_w, mod1_b, mod2_w, mod2_b, mod3_w, mod3_b);
    }
    // 2. weight square sums
    {
        int n = C2*C1 + C2*C2;
        k_wsq<<<(n + 255)/256, 256>>>(conv1_w, conv2_w);
    }
    // 3. demod scalars
    k_demod<<<(2*BB*C2 + 255)/256, 256>>>();
    // 4. upsample + modulate (s1)
    {
        size_t n = (size_t)BB*C1*NPIX;
        k_upmod<<<(unsigned)((n + 255)/256), 256>>>(x);
    }
    // 5. conv1 (input pre-modulated) -> g_h1, epilogue noise1 + lrelu
    k_conv3x3<C1, false><<<dim3(4, 16, BB*8), 128>>>(p_up, conv1_w, nullptr, p_e1, noise1, nw1, p_h1);
    // 6. conv2 (modulate by s2 at load) -> d_out h region, epilogue noise2 + lrelu
    k_conv3x3<C2, true ><<<dim3(4, 16, BB*8), 128>>>(p_h1, conv2_w, p_s2, p_e2, noise2, nw2, out_h);
    // 7. to_rgb + upsampled skip -> d_out rgb region
    k_rgb<<<dim3(NPIX/256, BB), 256>>>(out_h, rgb_w, skip, out_rgb);
}

// round 4
// speedup vs baseline: 1.5494x; 1.5486x over previous
#include <cuda_runtime.h>
#include <math.h>

#define BB   8
#define C1   512
#define C2   256
#define SD   512
#define H0   64
#define H1   128
#define NPIX   (H1*H1)      // 16384
#define NPIX0  (H0*H0)      // 4096

typedef unsigned long long ull;

// packed f32x2 helpers (sm_100+ PTX)
__device__ __forceinline__ void ffma2(ull& acc, ull a, ull b) {
    asm("fma.rn.f32x2 %0, %1, %2, %0;" : "+l"(acc) : "l"(a), "l"(b));
}
__device__ __forceinline__ ull bcast2(float v) {
    ull p;
    asm("mov.b64 %0, {%1, %1};" : "=l"(p) : "r"(__float_as_uint(v)));
    return p;
}
__device__ __forceinline__ void unpack2(ull p, float& lo, float& hi) {
    unsigned int a, b;
    asm("mov.b64 {%0, %1}, %2;" : "=r"(a), "=r"(b) : "l"(p));
    lo = __uint_as_float(a); hi = __uint_as_float(b);
}

// ---------------- scratch (device globals; no allocation) ----------------
__device__ float g_s1[BB*C1];
__device__ float g_s2[BB*C2];
__device__ float g_s3[BB*C2];
__device__ float g_e1[BB*C2];
__device__ float g_e2[BB*C2];
__device__ float g_wsq1[C2*C1];
__device__ float g_wsq2[C2*C2];
__device__ float g_up [(size_t)BB*C1*NPIX];   // 268 MB
__device__ float g_h1 [(size_t)BB*C2*NPIX];   // 134 MB

// ---------------- styles: s = style @ (mod_w/sqrt(S)).T + mod_b ----------------
__global__ void k_styles(const float* __restrict__ w1, const float* __restrict__ w2,
                         const float* __restrict__ m1w, const float* __restrict__ m1b,
                         const float* __restrict__ m2w, const float* __restrict__ m2b,
                         const float* __restrict__ m3w, const float* __restrict__ m3b)
{
    int t = blockIdx.x*blockDim.x + threadIdx.x;
    const float inv = rsqrtf((float)SD);
    if (t < BB*C1) {
        int b = t / C1, i = t % C1;
        float a = 0.f;
        for (int k = 0; k < SD; k++) a += w1[b*SD+k] * m1w[i*SD+k];
        g_s1[t] = a*inv + m1b[i];
    } else if (t < BB*C1 + BB*C2) {
        int u = t - BB*C1; int b = u / C2, i = u % C2;
        float a = 0.f;
        for (int k = 0; k < SD; k++) a += w2[b*SD+k] * m2w[i*SD+k];
        g_s2[u] = a*inv + m2b[i];
    } else if (t < BB*C1 + 2*BB*C2) {
        int u = t - BB*C1 - BB*C2; int b = u / C2, i = u % C2;
        float a = 0.f;
        for (int k = 0; k < SD; k++) a += w2[b*SD+k] * m3w[i*SD+k];
        g_s3[u] = a*inv + m3b[i];
    }
}

// ---------------- per-(o,i) sum of squared 3x3 taps ----------------
__global__ void k_wsq(const float* __restrict__ w1c, const float* __restrict__ w2c)
{
    int t = blockIdx.x*blockDim.x + threadIdx.x;
    if (t < C2*C1) {
        float a = 0.f;
        #pragma unroll
        for (int k = 0; k < 9; k++) { float v = w1c[t*9+k]; a += v*v; }
        g_wsq1[t] = a;
    } else if (t < C2*C1 + C2*C2) {
        int u = t - C2*C1;
        float a = 0.f;
        #pragma unroll
        for (int k = 0; k < 9; k++) { float v = w2c[u*9+k]; a += v*v; }
        g_wsq2[u] = a;
    }
}

// ---------------- e[b,o] = scale * rsqrt(scale^2 * sum_i wsq[o,i]*s[b,i]^2 + eps) ----------------
__global__ void k_demod()
{
    int t = blockIdx.x*blockDim.x + threadIdx.x;
    const float sc1 = rsqrtf((float)(C1*9));
    const float sc2 = rsqrtf((float)(C2*9));
    if (t < BB*C2) {
        int b = t / C2, o = t % C2;
        float a = 0.f;
        for (int i = 0; i < C1; i++) { float s = g_s1[b*C1+i]; a += g_wsq1[o*C1+i]*s*s; }
        g_e1[t] = sc1 * rsqrtf(sc1*sc1*a + 1e-8f);
    } else if (t < 2*BB*C2) {
        int u = t - BB*C2; int b = u / C2, o = u % C2;
        float a = 0.f;
        for (int i = 0; i < C2; i++) { float s = g_s2[b*C2+i]; a += g_wsq2[o*C2+i]*s*s; }
        g_e2[u] = sc2 * rsqrtf(sc2*sc2*a + 1e-8f);
    }
}

// ---------------- bilinear 2x upsample (half-pixel, clamped) with s1 folded in ----------------
__global__ void k_upmod(const float* __restrict__ x)
{
    size_t t = (size_t)blockIdx.x*blockDim.x + threadIdx.x;
    if (t >= (size_t)BB*C1*NPIX) return;
    int p  = (int)(t % NPIX);
    int bc = (int)(t / NPIX);
    int X = p % H1, Y = p / H1;
    float sy = Y*0.5f - 0.25f, sx = X*0.5f - 0.25f;
    int y0 = (int)floorf(sy), x0 = (int)floorf(sx);
    float fy = sy - (float)y0, fx = sx - (float)x0;
    int y0c = max(y0, 0), y1c = min(y0+1, H0-1);
    int x0c = max(x0, 0), x1c = min(x0+1, H0-1);
    const float* xp = x + (size_t)bc*NPIX0;
    float v = (1.f-fy)*((1.f-fx)*xp[y0c*H0+x0c] + fx*xp[y0c*H0+x1c])
            +      fy *((1.f-fx)*xp[y1c*H0+x0c] + fx*xp[y1c*H0+x1c]);
    g_up[t] = v * g_s1[bc];
}

// ---------------- 3x3 conv, pad 1: 32 o-chans x (32x8) pixel tile per block ----------------
// 128 threads: po = tid/32 (4 o-subgroups of 8 chans), tx = tid%32 (x col, 8 y rows each)
// Inner loop uses packed fma.rn.f32x2 across output-channel pairs; weight pairs
// come from shared via 8B-aligned LDS.64 (sW stride 34 keeps pair alignment).
template<int CIN, bool MODIN>
__global__ __launch_bounds__(128, 4)
void k_conv3x3(const float* __restrict__ in, const float* __restrict__ wgt,
               const float* __restrict__ smod, const float* __restrict__ emod,
               const float* __restrict__ noise, const float* __restrict__ nw,
               float* __restrict__ out)
{
    const int KC = 8, TO = 32;
    __shared__ float sIn[KC][10][34];
    __shared__ __align__(8) float sW [KC][9][TO+2];   // even stride -> o-pair 8B aligned

    int tid = threadIdx.x;
    int po  = tid >> 5;
    int tx  = tid & 31;
    int bz  = blockIdx.z;
    int b   = bz >> 3;
    int o0  = (bz & 7) * TO;
    int gx0 = blockIdx.x * 32;
    int gy0 = blockIdx.y * 8;

    // acc2[q][j]: packed pair over output chans (po*8 + 2q, +1), row j
    ull acc2[4][8];
    #pragma unroll
    for (int q = 0; q < 4; q++)
        #pragma unroll
        for (int j = 0; j < 8; j++) acc2[q][j] = 0ULL;

    for (int ci0 = 0; ci0 < CIN; ci0 += KC) {
        __syncthreads();
        // input tile 8 x 10 x 34 (halo, zero pad)
        for (int idx = tid; idx < KC*10*34; idx += 128) {
            int c = idx / 340, rem = idx % 340;
            int r = rem / 34, col = rem % 34;
            int gy = gy0 + r - 1, gx = gx0 + col - 1;
            float v = 0.f;
            if (gy >= 0 && gy < H1 && gx >= 0 && gx < H1) {
                v = in[(size_t)(b*CIN + ci0 + c)*NPIX + gy*H1 + gx];
                if (MODIN) v *= smod[b*CIN + ci0 + c];
            }
            sIn[c][r][col] = v;
        }
        // weights: per o, 72 consecutive floats (8 ci x 9 taps) -> coalesced
        for (int idx = tid; idx < TO*KC*9; idx += 128) {
            int o = idx / 72, rem = idx % 72;
            int c = rem / 9, tp = rem % 9;
            sW[c][tp][o] = wgt[(size_t)((o0 + o)*CIN + ci0 + c)*9 + tp];
        }
        __syncthreads();

        #pragma unroll
        for (int c = 0; c < KC; c++) {
            #pragma unroll
            for (int kx = 0; kx < 3; kx++) {
                ull vb[10];
                #pragma unroll
                for (int r = 0; r < 10; r++) vb[r] = bcast2(sIn[c][r][tx + kx]);
                #pragma unroll
                for (int ky = 0; ky < 3; ky++) {
                    ull wp[4];
                    #pragma unroll
                    for (int q = 0; q < 4; q++)
                        wp[q] = *reinterpret_cast<const ull*>(&sW[c][ky*3+kx][po*8 + q*2]);
                    #pragma unroll
                    for (int q = 0; q < 4; q++)
                        #pragma unroll
                        for (int j = 0; j < 8; j++)
                            ffma2(acc2[q][j], wp[q], vb[ky + j]);
                }
            }
        }
    }

    float nwv = nw[0];
    #pragma unroll
    for (int j = 0; j < 8; j++) {
        int gy = gy0 + j, gx = gx0 + tx;
        float nz = nwv * noise[(size_t)b*NPIX + gy*H1 + gx];
        #pragma unroll
        for (int q = 0; q < 4; q++) {
            int o = o0 + po*8 + q*2;
            float a0, a1; unpack2(acc2[q][j], a0, a1);
            float e0 = emod[b*C2 + o], e1 = emod[b*C2 + o + 1];
            float v0 = a0*e0 + nz; v0 = (v0 > 0.f) ? v0 : 0.2f*v0;
            float v1 = a1*e1 + nz; v1 = (v1 > 0.f) ? v1 : 0.2f*v1;
            out[(size_t)(b*C2 + o    )*NPIX + gy*H1 + gx] = v0;
            out[(size_t)(b*C2 + o + 1)*NPIX + gy*H1 + gx] = v1;
        }
    }
}

// ---------------- to_rgb 1x1 (no demod) + upsampled skip ----------------
__global__ void k_rgb(const float* __restrict__ h, const float* __restrict__ rgbw,
                      const float* __restrict__ skip, float* __restrict__ outrgb)
{
    int b = blockIdx.y;
    __shared__ float sw[3][C2];
    for (int i = threadIdx.x; i < 3*C2; i += blockDim.x) {
        int c = i / C2, o = i % C2;
        sw[c][o] = rgbw[c*C2 + o] * g_s3[b*C2 + o] * 0.0625f;  // scale3 = 1/sqrt(256)
    }
    __syncthreads();
    int p = blockIdx.x*blockDim.x + threadIdx.x;  // exact cover: 64*256 = 16384
    float a0 = 0.f, a1 = 0.f, a2 = 0.f;
    for (int o = 0; o < C2; o++) {
        float v = h[(size_t)(b*C2 + o)*NPIX + p];
        a0 += sw[0][o]*v; a1 += sw[1][o]*v; a2 += sw[2][o]*v;
    }
    int X = p % H1, Y = p / H1;
    float sy = Y*0.5f - 0.25f, sx = X*0.5f - 0.25f;
    int y0 = (int)floorf(sy), x0 = (int)floorf(sx);
    float fy = sy - (float)y0, fx = sx - (float)x0;
    int y0c = max(y0, 0), y1c = min(y0+1, H0-1);
    int x0c = max(x0, 0), x1c = min(x0+1, H0-1);
    float a[3] = {a0, a1, a2};
    #pragma unroll
    for (int c = 0; c < 3; c++) {
        const float* sp = skip + (size_t)(b*3 + c)*NPIX0;
        float bv = (1.f-fy)*((1.f-fx)*sp[y0c*H0+x0c] + fx*sp[y0c*H0+x1c])
                 +      fy *((1.f-fx)*sp[y1c*H0+x0c] + fx*sp[y1c*H0+x1c]);
        outrgb[(size_t)(b*3 + c)*NPIX + p] = a[c] + bv;
    }
}

// ---------------- launch ----------------
extern "C" void kernel_launch(void* const* d_in, const int* in_sizes, int n_in,
                              void* d_out, int out_size)
{
    const float* x       = (const float*)d_in[0];
    const float* w1      = (const float*)d_in[1];
    const float* w2      = (const float*)d_in[2];
    const float* skip    = (const float*)d_in[3];
    const float* noise1  = (const float*)d_in[4];
    const float* noise2  = (const float*)d_in[5];
    const float* conv1_w = (const float*)d_in[6];
    const float* mod1_w  = (const float*)d_in[7];
    const float* mod1_b  = (const float*)d_in[8];
    const float* conv2_w = (const float*)d_in[9];
    const float* mod2_w  = (const float*)d_in[10];
    const float* mod2_b  = (const float*)d_in[11];
    const float* rgb_w   = (const float*)d_in[12];
    const float* mod3_w  = (const float*)d_in[13];
    const float* mod3_b  = (const float*)d_in[14];
    const float* nw1     = (const float*)d_in[15];
    const float* nw2     = (const float*)d_in[16];
    float* out = (float*)d_out;

    float *p_up, *p_h1, *p_e1, *p_e2, *p_s2;
    cudaGetSymbolAddress((void**)&p_up, g_up);
    cudaGetSymbolAddress((void**)&p_h1, g_h1);
    cudaGetSymbolAddress((void**)&p_e1, g_e1);
    cudaGetSymbolAddress((void**)&p_e2, g_e2);
    cudaGetSymbolAddress((void**)&p_s2, g_s2);

    float* out_h   = out;                                // [8,256,128,128]
    float* out_rgb = out + (size_t)BB*C2*NPIX;           // [8,3,128,128]

    // 1. styles
    {
        int n = BB*C1 + 2*BB*C2;
        k_styles<<<(n + 255)/256, 256>>>(w1, w2, mod1_w, mod1_b, mod2_w, mod2_b, mod3_w, mod3_b);
    }
    // 2. weight square sums
    {
        int n = C2*C1 + C2*C2;
        k_wsq<<<(n + 255)/256, 256>>>(conv1_w, conv2_w);
    }
    // 3. demod scalars
    k_demod<<<(2*BB*C2 + 255)/256, 256>>>();
    // 4. upsample + modulate (s1)
    {
        size_t n = (size_t)BB*C1*NPIX;
        k_upmod<<<(unsigned)((n + 255)/256), 256>>>(x);
    }
    // 5. conv1 (input pre-modulated) -> g_h1, epilogue noise1 + lrelu
    k_conv3x3<C1, false><<<dim3(4, 16, BB*8), 128>>>(p_up, conv1_w, nullptr, p_e1, noise1, nw1, p_h1);
    // 6. conv2 (modulate by s2 at load) -> d_out h region, epilogue noise2 + lrelu
    k_conv3x3<C2, true ><<<dim3(4, 16, BB*8), 128>>>(p_h1, conv2_w, p_s2, p_e2, noise2, nw2, out_h);
    // 7. to_rgb + upsampled skip -> d_out rgb region
    k_rgb<<<dim3(NPIX/256, BB), 256>>>(out_h, rgb_w, skip, out_rgb);
}

// round 5
// speedup vs baseline: 1.5505x; 1.0007x over previous
#include <cuda_runtime.h>
#include <math.h>

#define BB   8
#define C1   512
#define C2   256
#define SD   512
#define H0   64
#define H1   128
#define NPIX   (H1*H1)      // 16384
#define NPIX0  (H0*H0)      // 4096

typedef unsigned long long ull;

// packed f32x2 helpers (sm_100+ PTX)
__device__ __forceinline__ void ffma2(ull& acc, ull a, ull b) {
    asm("fma.rn.f32x2 %0, %1, %2, %0;" : "+l"(acc) : "l"(a), "l"(b));
}
__device__ __forceinline__ ull bcast2(float v) {
    ull p;
    asm("mov.b64 %0, {%1, %1};" : "=l"(p) : "r"(__float_as_uint(v)));
    return p;
}
__device__ __forceinline__ void unpack2(ull p, float& lo, float& hi) {
    unsigned int a, b;
    asm("mov.b64 {%0, %1}, %2;" : "=r"(a), "=r"(b) : "l"(p));
    lo = __uint_as_float(a); hi = __uint_as_float(b);
}

// ---------------- scratch (device globals; no allocation) ----------------
__device__ float g_s1[BB*C1];
__device__ float g_s2[BB*C2];
__device__ float g_s3[BB*C2];
__device__ float g_e1[BB*C2];
__device__ float g_e2[BB*C2];
__device__ float g_wsq1[C2*C1];
__device__ float g_wsq2[C2*C2];
__device__ float g_up [(size_t)BB*C1*NPIX];   // 268 MB
__device__ float g_h1 [(size_t)BB*C2*NPIX];   // 134 MB

// ---------------- styles: s = style @ (mod_w/sqrt(S)).T + mod_b ----------------
__global__ void k_styles(const float* __restrict__ w1, const float* __restrict__ w2,
                         const float* __restrict__ m1w, const float* __restrict__ m1b,
                         const float* __restrict__ m2w, const float* __restrict__ m2b,
                         const float* __restrict__ m3w, const float* __restrict__ m3b)
{
    int t = blockIdx.x*blockDim.x + threadIdx.x;
    const float inv = rsqrtf((float)SD);
    if (t < BB*C1) {
        int b = t / C1, i = t % C1;
        float a = 0.f;
        for (int k = 0; k < SD; k++) a += w1[b*SD+k] * m1w[i*SD+k];
        g_s1[t] = a*inv + m1b[i];
    } else if (t < BB*C1 + BB*C2) {
        int u = t - BB*C1; int b = u / C2, i = u % C2;
        float a = 0.f;
        for (int k = 0; k < SD; k++) a += w2[b*SD+k] * m2w[i*SD+k];
        g_s2[u] = a*inv + m2b[i];
    } else if (t < BB*C1 + 2*BB*C2) {
        int u = t - BB*C1 - BB*C2; int b = u / C2, i = u % C2;
        float a = 0.f;
        for (int k = 0; k < SD; k++) a += w2[b*SD+k] * m3w[i*SD+k];
        g_s3[u] = a*inv + m3b[i];
    }
}

// ---------------- per-(o,i) sum of squared 3x3 taps ----------------
__global__ void k_wsq(const float* __restrict__ w1c, const float* __restrict__ w2c)
{
    int t = blockIdx.x*blockDim.x + threadIdx.x;
    if (t < C2*C1) {
        float a = 0.f;
        #pragma unroll
        for (int k = 0; k < 9; k++) { float v = w1c[t*9+k]; a += v*v; }
        g_wsq1[t] = a;
    } else if (t < C2*C1 + C2*C2) {
        int u = t - C2*C1;
        float a = 0.f;
        #pragma unroll
        for (int k = 0; k < 9; k++) { float v = w2c[u*9+k]; a += v*v; }
        g_wsq2[u] = a;
    }
}

// ---------------- e[b,o] = scale * rsqrt(scale^2 * sum_i wsq[o,i]*s[b,i]^2 + eps) ----------------
__global__ void k_demod()
{
    int t = blockIdx.x*blockDim.x + threadIdx.x;
    const float sc1 = rsqrtf((float)(C1*9));
    const float sc2 = rsqrtf((float)(C2*9));
    if (t < BB*C2) {
        int b = t / C2, o = t % C2;
        float a = 0.f;
        for (int i = 0; i < C1; i++) { float s = g_s1[b*C1+i]; a += g_wsq1[o*C1+i]*s*s; }
        g_e1[t] = sc1 * rsqrtf(sc1*sc1*a + 1e-8f);
    } else if (t < 2*BB*C2) {
        int u = t - BB*C2; int b = u / C2, o = u % C2;
        float a = 0.f;
        for (int i = 0; i < C2; i++) { float s = g_s2[b*C2+i]; a += g_wsq2[o*C2+i]*s*s; }
        g_e2[u] = sc2 * rsqrtf(sc2*sc2*a + 1e-8f);
    }
}

// ---------------- bilinear 2x upsample (half-pixel, clamped) with s1 folded in ----------------
__global__ void k_upmod(const float* __restrict__ x)
{
    size_t t = (size_t)blockIdx.x*blockDim.x + threadIdx.x;
    if (t >= (size_t)BB*C1*NPIX) return;
    int p  = (int)(t % NPIX);
    int bc = (int)(t / NPIX);
    int X = p % H1, Y = p / H1;
    float sy = Y*0.5f - 0.25f, sx = X*0.5f - 0.25f;
    int y0 = (int)floorf(sy), x0 = (int)floorf(sx);
    float fy = sy - (float)y0, fx = sx - (float)x0;
    int y0c = max(y0, 0), y1c = min(y0+1, H0-1);
    int x0c = max(x0, 0), x1c = min(x0+1, H0-1);
    const float* xp = x + (size_t)bc*NPIX0;
    float v = (1.f-fy)*((1.f-fx)*xp[y0c*H0+x0c] + fx*xp[y0c*H0+x1c])
            +      fy *((1.f-fx)*xp[y1c*H0+x0c] + fx*xp[y1c*H0+x1c]);
    g_up[t] = v * g_s1[bc];
}

// ---------------- 3x3 conv, pad 1: 32 o-chans x (32x8) pixel tile per block ----------------
// 128 threads: po = tid/32 (4 o-subgroups of 8 chans), tx = tid%32 (x col, 8 y rows each)
// Inner loop uses packed fma.rn.f32x2 across output-channel pairs; weight pairs
// come from shared via 8B-aligned LDS.64 (sW stride 34 keeps pair alignment).
template<int CIN, bool MODIN>
__global__ __launch_bounds__(128, 4)
void k_conv3x3(const float* __restrict__ in, const float* __restrict__ wgt,
               const float* __restrict__ smod, const float* __restrict__ emod,
               const float* __restrict__ noise, const float* __restrict__ nw,
               float* __restrict__ out)
{
    const int KC = 8, TO = 32;
    __shared__ float sIn[KC][10][34];
    __shared__ __align__(8) float sW [KC][9][TO+2];   // even stride -> o-pair 8B aligned

    int tid = threadIdx.x;
    int po  = tid >> 5;
    int tx  = tid & 31;
    int bz  = blockIdx.z;
    int b   = bz >> 3;
    int o0  = (bz & 7) * TO;
    int gx0 = blockIdx.x * 32;
    int gy0 = blockIdx.y * 8;

    // acc2[q][j]: packed pair over output chans (po*8 + 2q, +1), row j
    ull acc2[4][8];
    #pragma unroll
    for (int q = 0; q < 4; q++)
        #pragma unroll
        for (int j = 0; j < 8; j++) acc2[q][j] = 0ULL;

    for (int ci0 = 0; ci0 < CIN; ci0 += KC) {
        __syncthreads();
        // input tile 8 x 10 x 34 (halo, zero pad)
        for (int idx = tid; idx < KC*10*34; idx += 128) {
            int c = idx / 340, rem = idx % 340;
            int r = rem / 34, col = rem % 34;
            int gy = gy0 + r - 1, gx = gx0 + col - 1;
            float v = 0.f;
            if (gy >= 0 && gy < H1 && gx >= 0 && gx < H1) {
                v = in[(size_t)(b*CIN + ci0 + c)*NPIX + gy*H1 + gx];
                if (MODIN) v *= smod[b*CIN + ci0 + c];
            }
            sIn[c][r][col] = v;
        }
        // weights: per o, 72 consecutive floats (8 ci x 9 taps) -> coalesced
        for (int idx = tid; idx < TO*KC*9; idx += 128) {
            int o = idx / 72, rem = idx % 72;
            int c = rem / 9, tp = rem % 9;
            sW[c][tp][o] = wgt[(size_t)((o0 + o)*CIN + ci0 + c)*9 + tp];
        }
        __syncthreads();

        #pragma unroll
        for (int c = 0; c < KC; c++) {
            #pragma unroll
            for (int kx = 0; kx < 3; kx++) {
                ull vb[10];
                #pragma unroll
                for (int r = 0; r < 10; r++) vb[r] = bcast2(sIn[c][r][tx + kx]);
                #pragma unroll
                for (int ky = 0; ky < 3; ky++) {
                    ull wp[4];
                    #pragma unroll
                    for (int q = 0; q < 4; q++)
                        wp[q] = *reinterpret_cast<const ull*>(&sW[c][ky*3+kx][po*8 + q*2]);
                    #pragma unroll
                    for (int q = 0; q < 4; q++)
                        #pragma unroll
                        for (int j = 0; j < 8; j++)
                            ffma2(acc2[q][j], wp[q], vb[ky + j]);
                }
            }
        }
    }

    float nwv = nw[0];
    #pragma unroll
    for (int j = 0; j < 8; j++) {
        int gy = gy0 + j, gx = gx0 + tx;
        float nz = nwv * noise[(size_t)b*NPIX + gy*H1 + gx];
        #pragma unroll
        for (int q = 0; q < 4; q++) {
            int o = o0 + po*8 + q*2;
            float a0, a1; unpack2(acc2[q][j], a0, a1);
            float e0 = emod[b*C2 + o], e1 = emod[b*C2 + o + 1];
            float v0 = a0*e0 + nz; v0 = (v0 > 0.f) ? v0 : 0.2f*v0;
            float v1 = a1*e1 + nz; v1 = (v1 > 0.f) ? v1 : 0.2f*v1;
            out[(size_t)(b*C2 + o    )*NPIX + gy*H1 + gx] = v0;
            out[(size_t)(b*C2 + o + 1)*NPIX + gy*H1 + gx] = v1;
        }
    }
}

// ---------------- to_rgb 1x1 (no demod) + upsampled skip ----------------
__global__ void k_rgb(const float* __restrict__ h, const float* __restrict__ rgbw,
                      const float* __restrict__ skip, float* __restrict__ outrgb)
{
    int b = blockIdx.y;
    __shared__ float sw[3][C2];
    for (int i = threadIdx.x; i < 3*C2; i += blockDim.x) {
        int c = i / C2, o = i % C2;
        sw[c][o] = rgbw[c*C2 + o] * g_s3[b*C2 + o] * 0.0625f;  // scale3 = 1/sqrt(256)
    }
    __syncthreads();
    int p = blockIdx.x*blockDim.x + threadIdx.x;  // exact cover: 64*256 = 16384
    float a0 = 0.f, a1 = 0.f, a2 = 0.f;
    for (int o = 0; o < C2; o++) {
        float v = h[(size_t)(b*C2 + o)*NPIX + p];
        a0 += sw[0][o]*v; a1 += sw[1][o]*v; a2 += sw[2][o]*v;
    }
    int X = p % H1, Y = p / H1;
    float sy = Y*0.5f - 0.25f, sx = X*0.5f - 0.25f;
    int y0 = (int)floorf(sy), x0 = (int)floorf(sx);
    float fy = sy - (float)y0, fx = sx - (float)x0;
    int y0c = max(y0, 0), y1c = min(y0+1, H0-1);
    int x0c = max(x0, 0), x1c = min(x0+1, H0-1);
    float a[3] = {a0, a1, a2};
    #pragma unroll
    for (int c = 0; c < 3; c++) {
        const float* sp = skip + (size_t)(b*3 + c)*NPIX0;
        float bv = (1.f-fy)*((1.f-fx)*sp[y0c*H0+x0c] + fx*sp[y0c*H0+x1c])
                 +      fy *((1.f-fx)*sp[y1c*H0+x0c] + fx*sp[y1c*H0+x1c]);
        outrgb[(size_t)(b*3 + c)*NPIX + p] = a[c] + bv;
    }
}

// ---------------- launch ----------------
extern "C" void kernel_launch(void* const* d_in, const int* in_sizes, int n_in,
                              void* d_out, int out_size)
{
    const float* x       = (const float*)d_in[0];
    const float* w1      = (const float*)d_in[1];
    const float* w2      = (const float*)d_in[2];
    const float* skip    = (const float*)d_in[3];
    const float* noise1  = (const float*)d_in[4];
    const float* noise2  = (const float*)d_in[5];
    const float* conv1_w = (const float*)d_in[6];
    const float* mod1_w  = (const float*)d_in[7];
    const float* mod1_b  = (const float*)d_in[8];
    const float* conv2_w = (const float*)d_in[9];
    const float* mod2_w  = (const float*)d_in[10];
    const float* mod2_b  = (const float*)d_in[11];
    const float* rgb_w   = (const float*)d_in[12];
    const float* mod3_w  = (const float*)d_in[13];
    const float* mod3_b  = (const float*)d_in[14];
    const float* nw1     = (const float*)d_in[15];
    const float* nw2     = (const float*)d_in[16];
    float* out = (float*)d_out;

    float *p_up, *p_h1, *p_e1, *p_e2, *p_s2;
    cudaGetSymbolAddress((void**)&p_up, g_up);
    cudaGetSymbolAddress((void**)&p_h1, g_h1);
    cudaGetSymbolAddress((void**)&p_e1, g_e1);
    cudaGetSymbolAddress((void**)&p_e2, g_e2);
    cudaGetSymbolAddress((void**)&p_s2, g_s2);

    float* out_h   = out;                                // [8,256,128,128]
    float* out_rgb = out + (size_t)BB*C2*NPIX;           // [8,3,128,128]

    // 1. styles
    {
        int n = BB*C1 + 2*BB*C2;
        k_styles<<<(n + 255)/256, 256>>>(w1, w2, mod1_w, mod1_b, mod2_w, mod2_b, mod3_w, mod3_b);
    }
    // 2. weight square sums
    {
        int n = C2*C1 + C2*C2;
        k_wsq<<<(n + 255)/256, 256>>>(conv1_w, conv2_w);
    }
    // 3. demod scalars
    k_demod<<<(2*BB*C2 + 255)/256, 256>>>();
    // 4. upsample + modulate (s1)
    {
        size_t n = (size_t)BB*C1*NPIX;
        k_upmod<<<(unsigned)((n + 255)/256), 256>>>(x);
    }
    // 5. conv1 (input pre-modulated) -> g_h1, epilogue noise1 + lrelu
    k_conv3x3<C1, false><<<dim3(4, 16, BB*8), 128>>>(p_up, conv1_w, nullptr, p_e1, noise1, nw1, p_h1);
    // 6. conv2 (modulate by s2 at load) -> d_out h region, epilogue noise2 + lrelu
    k_conv3x3<C2, true ><<<dim3(4, 16, BB*8), 128>>>(p_h1, conv2_w, p_s2, p_e2, noise2, nw2, out_h);
    // 7. to_rgb + upsampled skip -> d_out rgb region
    k_rgb<<<dim3(NPIX/256, BB), 256>>>(out_h, rgb_w, skip, out_rgb);
}